// round 13
// baseline (speedup 1.0000x reference)
#include <cuda_runtime.h>
#include <cuda_fp16.h>

#define B_ 2
#define N_ 2048
#define C_ 1024
#define H_ 16
#define D_ 64
#define SCALE_ 0.125f
#define M_TOT (B_ * N_)
#define C4_ (4 * C_)
#define K2_ (2 * C_)

// ---------------- scratch (device globals; no allocation) ----------------
__device__ __half g_acat[(size_t)M_TOT * K2_];     // [M][2C] = [x | e]
__device__ __half g_w1[(size_t)C_ * 3 * C_];       // [1024][3C] = [Wq | Wv | Wg]
__device__ __half g_w2[(size_t)K2_ * C_];          // [2048][C]  = [Wk ; Ws]
__device__ __half g_wp_h[(size_t)C_ * C_];
__device__ __half g_qkvg_h[(size_t)M_TOT * C4_];   // [M][4C] = q|v|gate|(k+s)
__device__ __half g_att_h[(size_t)M_TOT * C_];

// ---------------- helpers -------------------------------------------------
__device__ __forceinline__ void ldm_x4(unsigned r[4], const void* p) {
    unsigned a = (unsigned)__cvta_generic_to_shared(p);
    asm volatile("ldmatrix.sync.aligned.m8n8.x4.shared.b16 {%0,%1,%2,%3}, [%4];"
                 : "=r"(r[0]), "=r"(r[1]), "=r"(r[2]), "=r"(r[3]) : "r"(a));
}
__device__ __forceinline__ void ldm_x4t(unsigned r[4], const void* p) {
    unsigned a = (unsigned)__cvta_generic_to_shared(p);
    asm volatile("ldmatrix.sync.aligned.m8n8.x4.trans.shared.b16 {%0,%1,%2,%3}, [%4];"
                 : "=r"(r[0]), "=r"(r[1]), "=r"(r[2]), "=r"(r[3]) : "r"(a));
}
__device__ __forceinline__ void mma_h(float c[4], const unsigned a[4], const unsigned b[2]) {
    asm volatile("mma.sync.aligned.m16n8k16.row.col.f32.f16.f16.f32 "
                 "{%0,%1,%2,%3}, {%4,%5,%6,%7}, {%8,%9}, {%0,%1,%2,%3};"
                 : "+f"(c[0]), "+f"(c[1]), "+f"(c[2]), "+f"(c[3])
                 : "r"(a[0]), "r"(a[1]), "r"(a[2]), "r"(a[3]), "r"(b[0]), "r"(b[1]));
}
__device__ __forceinline__ unsigned h2u(__half2 h) { return *reinterpret_cast<unsigned*>(&h); }
__device__ __forceinline__ unsigned hmul2u(unsigned a, __half2 s) {
    __half2 r = __hmul2(*reinterpret_cast<__half2*>(&a), s);
    return h2u(r);
}

// ---------------- fused fp32 -> fp16 convert ------------------------------
__device__ __forceinline__ void cv16(const float* __restrict__ in,
                                     __half* __restrict__ out, int i) {
    float4 a0 = *(const float4*)(in + i);
    float4 a1 = *(const float4*)(in + i + 4);
    float4 a2 = *(const float4*)(in + i + 8);
    float4 a3 = *(const float4*)(in + i + 12);
    uint4 u0 = { h2u(__floats2half2_rn(a0.x, a0.y)), h2u(__floats2half2_rn(a0.z, a0.w)),
                 h2u(__floats2half2_rn(a1.x, a1.y)), h2u(__floats2half2_rn(a1.z, a1.w)) };
    uint4 u1 = { h2u(__floats2half2_rn(a2.x, a2.y)), h2u(__floats2half2_rn(a2.z, a2.w)),
                 h2u(__floats2half2_rn(a3.x, a3.y)), h2u(__floats2half2_rn(a3.z, a3.w)) };
    *(uint4*)(out + i) = u0;
    *(uint4*)(out + i + 8) = u1;
}
__device__ __forceinline__ void cv16p(const float* __restrict__ in, __half* op, int i) {
    float4 a0 = *(const float4*)(in + i);
    float4 a1 = *(const float4*)(in + i + 4);
    float4 a2 = *(const float4*)(in + i + 8);
    float4 a3 = *(const float4*)(in + i + 12);
    uint4 u0 = { h2u(__floats2half2_rn(a0.x, a0.y)), h2u(__floats2half2_rn(a0.z, a0.w)),
                 h2u(__floats2half2_rn(a1.x, a1.y)), h2u(__floats2half2_rn(a1.z, a1.w)) };
    uint4 u1 = { h2u(__floats2half2_rn(a2.x, a2.y)), h2u(__floats2half2_rn(a2.z, a2.w)),
                 h2u(__floats2half2_rn(a3.x, a3.y)), h2u(__floats2half2_rn(a3.z, a3.w)) };
    *(uint4*)op = u0;
    *(uint4*)(op + 8) = u1;
}
// block ranges (4096 elems/block):
// [0,1024) x->acat[:,0:1024), [1024,2048) e->acat[:,1024:2048),
// [2048,2816) Wqkv split->w1/w2, [2816,3072) Wg->w1 col+2048,
// [3072,3328) Ws->w2 row+1024, [3328,3584) Wp plain
__global__ void cvt_all(const float* __restrict__ x, const float* __restrict__ e,
                        const float* __restrict__ wqkv, const float* __restrict__ wg,
                        const float* __restrict__ ws, const float* __restrict__ wp,
                        __half* __restrict__ acat, __half* __restrict__ w1,
                        __half* __restrict__ w2, __half* __restrict__ wph)
{
    int blk = blockIdx.x;
    int t16 = threadIdx.x * 16;
    if (blk < 1024) {
        int i = blk * 4096 + t16;
        int row = i >> 10, col = i & 1023;
        cv16p(x, acat + (size_t)row * K2_ + col, i);
    } else if (blk < 2048) {
        int i = (blk - 1024) * 4096 + t16;
        int row = i >> 10, col = i & 1023;
        cv16p(e, acat + (size_t)row * K2_ + C_ + col, i);
    } else if (blk < 2816) {
        int i = (blk - 2048) * 4096 + t16;          // Wqkv [1024][3072]
        int row = i / 3072, col = i - row * 3072;
        __half* op;
        if (col < 1024)       op = w1 + (size_t)row * 3072 + col;              // q
        else if (col < 2048)  op = w2 + (size_t)row * C_ + (col - 1024);       // k
        else                  op = w1 + (size_t)row * 3072 + 1024 + (col - 2048); // v
        cv16p(wqkv, op, i);
    } else if (blk < 3072) {
        int i = (blk - 2816) * 4096 + t16;          // Wg [1024][1024]
        int row = i >> 10, col = i & 1023;
        cv16p(wg, w1 + (size_t)row * 3072 + 2048 + col, i);
    } else if (blk < 3328) {
        int i = (blk - 3072) * 4096 + t16;          // Ws [1024][1024]
        int row = i >> 10, col = i & 1023;
        cv16p(ws, w2 + (size_t)(1024 + row) * C_ + col, i);
    } else {
        cv16(wp, wph, (blk - 3328) * 4096 + t16);
    }
}

// ---------------- fp16 GEMM core (R10-proven: 128x128, 2-stage) ------------
// BK=32, 256 thr (8 warps 2x4), warp tile 64x32, m16n8k16.
// Kloop: summed K; Kstride: A row stride; Nb: B row stride; Nc: C row stride.
template <int BIAS, int HOUT>
__device__ __forceinline__ void gemm_body(
    const __half* __restrict__ A, const __half* __restrict__ Bw,
    const float* __restrict__ bias, void* __restrict__ Cout,
    int Kloop, int Kstride, int Nb, int Nc, int m_blk, int n_blk,
    __half (*As)[128 * 40], __half (*Bs)[32 * 136])
{
    const int tid = threadIdx.x;
    const int wid = tid >> 5, lane = tid & 31;
    const int wm = (wid & 1) * 64, wn = (wid >> 1) * 32;

    const int arow = tid >> 2, acol = (tid & 3) * 8;
    const int brow = tid >> 4, bcol = (tid & 15) * 8;

    uint4 pa[2], pb[2];
    auto ld = [&](int kb) {
#pragma unroll
        for (int p = 0; p < 2; p++) {
            pa[p] = *(const uint4*)(A + (size_t)(m_blk + p * 64 + arow) * Kstride + kb * 32 + acol);
            pb[p] = *(const uint4*)(Bw + (size_t)(kb * 32 + p * 16 + brow) * Nb + n_blk + bcol);
        }
    };
    auto st = [&](int s) {
#pragma unroll
        for (int p = 0; p < 2; p++) {
            *(uint4*)&As[s][(p * 64 + arow) * 40 + acol] = pa[p];
            *(uint4*)&Bs[s][(p * 16 + brow) * 136 + bcol] = pb[p];
        }
    };

    float acc[4][4][4] = {};
    ld(0); st(0);
    __syncthreads();

    const int KB = Kloop / 32;
    for (int kb = 0; kb < KB; kb++) {
        if (kb + 1 < KB) ld(kb + 1);
        const int cs = kb & 1;
#pragma unroll
        for (int ks = 0; ks < 2; ks++) {
            unsigned af[4][4], bf[4][2];
#pragma unroll
            for (int mt = 0; mt < 4; mt++)
                ldm_x4(af[mt], &As[cs][(wm + mt * 16 + (lane & 15)) * 40 + ks * 16 + (lane >> 4) * 8]);
#pragma unroll
            for (int sl = 0; sl < 2; sl++) {
                unsigned tr[4];
                ldm_x4t(tr, &Bs[cs][(ks * 16 + (lane & 7) + ((lane >> 3) & 1) * 8) * 136
                                    + wn + sl * 16 + (lane >> 4) * 8]);
                bf[sl * 2 + 0][0] = tr[0]; bf[sl * 2 + 0][1] = tr[1];
                bf[sl * 2 + 1][0] = tr[2]; bf[sl * 2 + 1][1] = tr[3];
            }
#pragma unroll
            for (int mt = 0; mt < 4; mt++)
#pragma unroll
                for (int nt = 0; nt < 4; nt++)
                    mma_h(acc[mt][nt], af[mt], bf[nt]);
        }
        if (kb + 1 < KB) st((kb + 1) & 1);
        __syncthreads();
    }

    const int g = lane >> 2, t2 = (lane & 3) * 2;
#pragma unroll
    for (int mt = 0; mt < 4; mt++) {
#pragma unroll
        for (int nt = 0; nt < 4; nt++) {
            int col = n_blk + wn + nt * 8 + t2;
            size_t r0 = (size_t)(m_blk + wm + mt * 16 + g);
            if (HOUT) {
                __half* Ch = (__half*)Cout;
                *(__half2*)(Ch + r0 * Nc + col) = __floats2half2_rn(acc[mt][nt][0], acc[mt][nt][1]);
                *(__half2*)(Ch + (r0 + 8) * Nc + col) = __floats2half2_rn(acc[mt][nt][2], acc[mt][nt][3]);
            } else {
                float* Cf = (float*)Cout;
                float b0 = 0.f, b1 = 0.f;
                if (BIAS) { b0 = bias[col]; b1 = bias[col + 1]; }
                float2 v0 = { acc[mt][nt][0] + b0, acc[mt][nt][1] + b1 };
                float2 v1 = { acc[mt][nt][2] + b0, acc[mt][nt][3] + b1 };
                *(float2*)(Cf + r0 * Nc + col) = v0;
                *(float2*)(Cf + (r0 + 8) * Nc + col) = v1;
            }
        }
    }
}

// fused: bx<24 -> qvg = acat_x @ W1 (K=1024, cols [0,3C));
//        bx>=24 -> kps = [x|e] @ W2 (K=2048, cols [3C,4C))
__global__ __launch_bounds__(256) void gemm_fused(
    const __half* __restrict__ acat, const __half* __restrict__ w1,
    const __half* __restrict__ w2, __half* __restrict__ qkvg)
{
    __shared__ __half As[2][128 * 40];
    __shared__ __half Bs[2][32 * 136];
    const int bx = blockIdx.x;
    const int m_blk = blockIdx.y * 128;
    if (bx < 24)
        gemm_body<0, 1>(acat, w1, nullptr, qkvg,
                        C_, K2_, 3 * C_, C4_, m_blk, bx * 128, As, Bs);
    else
        gemm_body<0, 1>(acat, w2, nullptr, qkvg + 3 * C_,
                        K2_, K2_, C_, C4_, m_blk, (bx - 24) * 128, As, Bs);
}

// proj: out = att @ W_proj + bias (fp32 out)
__global__ __launch_bounds__(256) void gemm_proj(
    const __half* __restrict__ atth, const __half* __restrict__ wp,
    const float* __restrict__ bias, float* __restrict__ out)
{
    __shared__ __half As[2][128 * 40];
    __shared__ __half Bs[2][32 * 136];
    gemm_body<1, 0>(atth, wp, bias, out,
                    C_, C_, C_, C_, blockIdx.y * 128, blockIdx.x * 128, As, Bs);
}

// ---------------- fp16 flash attention: P in regs, kps precomputed ---------
// grid (N/128, H, B), 256 thr (8 warps). Warp w owns q-rows 16w..16w+15.
// qkvg rows [q | v | gate | k+s], stride 4C. Scale folded into Q load.
__global__ __launch_bounds__(256) void flash_h(
    const __half* __restrict__ qkvg, __half* __restrict__ outp)
{
    extern __shared__ __half smh[];
    __half* Qs = smh;                        // [128][72] (staging only)
    __half* Ks = smh + 128 * 72;             // 2 x [64][72]
    __half* Vs = smh + 128 * 72 + 2 * 64 * 72;

    const int qt = blockIdx.x, h = blockIdx.y, b = blockIdx.z;
    const int tid = threadIdx.x;
    const int wid = tid >> 5, lane = tid & 31;
    const size_t qbase = (size_t)(b * N_ + qt * 128);

    const int lr = tid >> 3, lc = (tid & 7) * 8;

    uint4 rk[2], rv[2];
    auto ldkv = [&](int kt) {
        const size_t kvb = (size_t)(b * N_ + kt * 64);
#pragma unroll
        for (int p = 0; p < 2; p++) {
            int r = p * 32 + lr;
            rk[p] = *(const uint4*)(qkvg + (kvb + r) * C4_ + 3 * C_ + h * D_ + lc);  // k+s
            rv[p] = *(const uint4*)(qkvg + (kvb + r) * C4_ + C_ + h * D_ + lc);      // v
        }
    };
    auto stkv = [&](int s) {
#pragma unroll
        for (int p = 0; p < 2; p++) {
            int r = p * 32 + lr;
            *(uint4*)&Ks[s * (64 * 72) + r * 72 + lc] = rk[p];
            *(uint4*)&Vs[s * (64 * 72) + r * 72 + lc] = rv[p];
        }
    };

    // ---- prefetch KV tile 0; Q -> smem with scale folded ----
    ldkv(0);
    const __half2 sc2 = __float2half2_rn(SCALE_);
#pragma unroll
    for (int p = 0; p < 4; p++) {
        int r = p * 32 + lr;
        uint4 q4 = *(const uint4*)(qkvg + (qbase + r) * C4_ + h * D_ + lc);
        q4.x = hmul2u(q4.x, sc2); q4.y = hmul2u(q4.y, sc2);
        q4.z = hmul2u(q4.z, sc2); q4.w = hmul2u(q4.w, sc2);
        *(uint4*)&Qs[r * 72 + lc] = q4;
    }
    __syncthreads();

    unsigned qf[4][4];
#pragma unroll
    for (int kd = 0; kd < 4; kd++)
        ldm_x4(qf[kd], &Qs[(wid * 16 + (lane & 15)) * 72 + kd * 16 + (lane >> 4) * 8]);
    stkv(0);
    __syncthreads();

    float o[8][4] = {};
    float m0v = -1e30f, m1v = -1e30f, l0v = 0.f, l1v = 0.f;

    for (int kt = 0; kt < N_ / 64; kt++) {
        const int cs = kt & 1;
        const __half* Kc = Ks + cs * (64 * 72);
        const __half* Vc = Vs + cs * (64 * 72);

        // ---- S = Q (K+s)^T : 16 x 64 per warp ----
        float sc[8][4] = {};
#pragma unroll
        for (int kd = 0; kd < 4; kd++) {
            unsigned bf[8][2];
#pragma unroll
            for (int sp = 0; sp < 4; sp++) {
                unsigned tr[4];
                ldm_x4(tr, &Kc[(sp * 16 + (lane & 7) + (lane >> 4) * 8) * 72
                               + kd * 16 + ((lane >> 3) & 1) * 8]);
                bf[sp * 2 + 0][0] = tr[0]; bf[sp * 2 + 0][1] = tr[1];
                bf[sp * 2 + 1][0] = tr[2]; bf[sp * 2 + 1][1] = tr[3];
            }
#pragma unroll
            for (int nt = 0; nt < 8; nt++)
                mma_h(sc[nt], qf[kd], bf[nt]);
        }

        // ---- online softmax; P built directly as mma A-fragments ----
        float rmax0 = -1e30f, rmax1 = -1e30f;
#pragma unroll
        for (int nt = 0; nt < 8; nt++) {
            rmax0 = fmaxf(rmax0, fmaxf(sc[nt][0], sc[nt][1]));
            rmax1 = fmaxf(rmax1, fmaxf(sc[nt][2], sc[nt][3]));
        }
#pragma unroll
        for (int off = 1; off <= 2; off <<= 1) {
            rmax0 = fmaxf(rmax0, __shfl_xor_sync(~0u, rmax0, off));
            rmax1 = fmaxf(rmax1, __shfl_xor_sync(~0u, rmax1, off));
        }
        float mn0 = fmaxf(m0v, rmax0), mn1 = fmaxf(m1v, rmax1);
        float cf0 = __expf(m0v - mn0), cf1 = __expf(m1v - mn1);
        m0v = mn0; m1v = mn1;
        float rs0 = 0.f, rs1 = 0.f;
        unsigned pf[4][4];
#pragma unroll
        for (int nt = 0; nt < 8; nt++) {
            float p0 = __expf(sc[nt][0] - mn0);
            float p1 = __expf(sc[nt][1] - mn0);
            float p2 = __expf(sc[nt][2] - mn1);
            float p3 = __expf(sc[nt][3] - mn1);
            rs0 += p0 + p1; rs1 += p2 + p3;
            const int kk = nt >> 1, hi = (nt & 1) * 2;
            pf[kk][hi + 0] = h2u(__floats2half2_rn(p0, p1));  // row g
            pf[kk][hi + 1] = h2u(__floats2half2_rn(p2, p3));  // row g+8
        }
#pragma unroll
        for (int off = 1; off <= 2; off <<= 1) {
            rs0 += __shfl_xor_sync(~0u, rs0, off);
            rs1 += __shfl_xor_sync(~0u, rs1, off);
        }
        l0v = l0v * cf0 + rs0;
        l1v = l1v * cf1 + rs1;
#pragma unroll
        for (int nt = 0; nt < 8; nt++) {
            o[nt][0] *= cf0; o[nt][1] *= cf0;
            o[nt][2] *= cf1; o[nt][3] *= cf1;
        }

        // ---- prefetch next KV (sc regs dead; hidden under PV mma) ----
        if (kt + 1 < N_ / 64) ldkv(kt + 1);

        // ---- O += P V ----
#pragma unroll
        for (int kk = 0; kk < 4; kk++) {
            unsigned bf[8][2];
#pragma unroll
            for (int ds = 0; ds < 4; ds++) {
                unsigned tr[4];
                ldm_x4t(tr, &Vc[(kk * 16 + (lane & 7) + ((lane >> 3) & 1) * 8) * 72
                                + ds * 16 + (lane >> 4) * 8]);
                bf[ds * 2 + 0][0] = tr[0]; bf[ds * 2 + 0][1] = tr[1];
                bf[ds * 2 + 1][0] = tr[2]; bf[ds * 2 + 1][1] = tr[3];
            }
#pragma unroll
            for (int nt = 0; nt < 8; nt++)
                mma_h(o[nt], pf[kk], bf[nt]);
        }

        if (kt + 1 < N_ / 64) stkv((kt + 1) & 1);
        __syncthreads();
    }

    // ---- epilogue: normalize, gate (qkvg col 2C), write fp16 att ----
    const int g = lane >> 2, t = lane & 3;
    float inv0 = 1.f / l0v, inv1 = 1.f / l1v;
    size_t r0 = qbase + wid * 16 + g;
#pragma unroll
    for (int nt = 0; nt < 8; nt++) {
        int col = h * D_ + nt * 8 + 2 * t;
        float2 g0 = __half22float2(*(const __half2*)(qkvg + r0 * C4_ + 2 * C_ + col));
        float2 g1 = __half22float2(*(const __half2*)(qkvg + (r0 + 8) * C4_ + 2 * C_ + col));
        *(__half2*)(outp + r0 * C_ + col) =
            __floats2half2_rn(o[nt][0] * inv0 * g0.x, o[nt][1] * inv0 * g0.y);
        *(__half2*)(outp + (r0 + 8) * C_ + col) =
            __floats2half2_rn(o[nt][2] * inv1 * g1.x, o[nt][3] * inv1 * g1.y);
    }
}

// ---------------- launch ------------------------------------------------
extern "C" void kernel_launch(void* const* d_in, const int* in_sizes, int n_in,
                              void* d_out, int out_size)
{
    (void)in_sizes; (void)n_in; (void)out_size;
    const float* x    = (const float*)d_in[0];
    const float* e    = (const float*)d_in[1];
    const float* Wqkv = (const float*)d_in[2];
    const float* Ws   = (const float*)d_in[3];
    const float* Wg   = (const float*)d_in[4];
    const float* Wp   = (const float*)d_in[5];
    const float* bp   = (const float*)d_in[6];
    float* out = (float*)d_out;

    __half *acat, *w1, *w2, *wph, *qkvgh, *atth;
    cudaGetSymbolAddress((void**)&acat,  g_acat);
    cudaGetSymbolAddress((void**)&w1,    g_w1);
    cudaGetSymbolAddress((void**)&w2,    g_w2);
    cudaGetSymbolAddress((void**)&wph,   g_wp_h);
    cudaGetSymbolAddress((void**)&qkvgh, g_qkvg_h);
    cudaGetSymbolAddress((void**)&atth,  g_att_h);

    const int flash_smem = (128 + 2 * 64 + 2 * 64) * 72 * 2;
    static int smem_set = 0;
    if (!smem_set) {
        cudaFuncSetAttribute(flash_h, cudaFuncAttributeMaxDynamicSharedMemorySize, flash_smem);
        smem_set = 1;
    }

    // 1) all fp32->fp16 conversions + weight re-layout in one launch
    cvt_all<<<3584, 256>>>(x, e, Wqkv, Wg, Ws, Wp, acat, w1, w2, wph);

    // 2) qkvg = [ x@[Wq|Wv|Wg] | [x|e]@[Wk;Ws] ] in one launch
    gemm_fused<<<dim3(32, M_TOT / 128), 256>>>(acat, w1, w2, qkvgh);

    // 3) fused flash attention (kps precomputed, scale fold, gate fold, P in regs)
    flash_h<<<dim3(N_ / 128, H_, B_), 256, flash_smem>>>(qkvgh, atth);

    // 4) out = att @ W_proj + b_proj
    gemm_proj<<<dim3(C_ / 128, M_TOT / 128), 256>>>(atth, wph, bp, out);
}

// round 14
// speedup vs baseline: 1.4555x; 1.4555x over previous
#include <cuda_runtime.h>
#include <cuda_fp16.h>

#define B_ 2
#define N_ 2048
#define C_ 1024
#define H_ 16
#define D_ 64
#define SCALE_ 0.125f
#define M_TOT (B_ * N_)
#define C4_ (4 * C_)

// ---------------- scratch (device globals; no allocation) ----------------
__device__ __half g_x_h[(size_t)M_TOT * C_];
__device__ __half g_e_h[(size_t)M_TOT * C_];
__device__ __half g_wqkvg_h[(size_t)C_ * C4_];     // [K][4C] = [Wqkv | Wgate]
__device__ __half g_ws_h[(size_t)C_ * C_];
__device__ __half g_wp_h[(size_t)C_ * C_];
__device__ __half g_qkvg_h[(size_t)M_TOT * C4_];   // [M][4C] = q|k|v|gate
__device__ __half g_s_h[(size_t)M_TOT * C_];
__device__ __half g_att_h[(size_t)M_TOT * C_];

// ---------------- helpers -------------------------------------------------
__device__ __forceinline__ void ldm_x4(unsigned r[4], const void* p) {
    unsigned a = (unsigned)__cvta_generic_to_shared(p);
    asm volatile("ldmatrix.sync.aligned.m8n8.x4.shared.b16 {%0,%1,%2,%3}, [%4];"
                 : "=r"(r[0]), "=r"(r[1]), "=r"(r[2]), "=r"(r[3]) : "r"(a));
}
__device__ __forceinline__ void ldm_x4t(unsigned r[4], const void* p) {
    unsigned a = (unsigned)__cvta_generic_to_shared(p);
    asm volatile("ldmatrix.sync.aligned.m8n8.x4.trans.shared.b16 {%0,%1,%2,%3}, [%4];"
                 : "=r"(r[0]), "=r"(r[1]), "=r"(r[2]), "=r"(r[3]) : "r"(a));
}
__device__ __forceinline__ void mma_h(float c[4], const unsigned a[4], const unsigned b[2]) {
    asm volatile("mma.sync.aligned.m16n8k16.row.col.f32.f16.f16.f32 "
                 "{%0,%1,%2,%3}, {%4,%5,%6,%7}, {%8,%9}, {%0,%1,%2,%3};"
                 : "+f"(c[0]), "+f"(c[1]), "+f"(c[2]), "+f"(c[3])
                 : "r"(a[0]), "r"(a[1]), "r"(a[2]), "r"(a[3]), "r"(b[0]), "r"(b[1]));
}
__device__ __forceinline__ unsigned h2u(__half2 h) { return *reinterpret_cast<unsigned*>(&h); }
__device__ __forceinline__ unsigned hadd2u(unsigned a, unsigned b) {
    __half2 r = __hadd2(*reinterpret_cast<__half2*>(&a), *reinterpret_cast<__half2*>(&b));
    return h2u(r);
}
__device__ __forceinline__ unsigned hmul2u(unsigned a, __half2 s) {
    __half2 r = __hmul2(*reinterpret_cast<__half2*>(&a), s);
    return h2u(r);
}
__device__ __forceinline__ void cpa16(__half* dst, const __half* src) {
    unsigned d = (unsigned)__cvta_generic_to_shared(dst);
    asm volatile("cp.async.cg.shared.global [%0], [%1], 16;" :: "r"(d), "l"(src));
}
#define CP_COMMIT() asm volatile("cp.async.commit_group;")

// ---------------- fused fp32 -> fp16 convert (16 elems/thread, MLP=4) ------
__device__ __forceinline__ void cv16(const float* __restrict__ in,
                                     __half* __restrict__ out, int i) {
    float4 a0 = *(const float4*)(in + i);
    float4 a1 = *(const float4*)(in + i + 4);
    float4 a2 = *(const float4*)(in + i + 8);
    float4 a3 = *(const float4*)(in + i + 12);
    uint4 u0 = { h2u(__floats2half2_rn(a0.x, a0.y)), h2u(__floats2half2_rn(a0.z, a0.w)),
                 h2u(__floats2half2_rn(a1.x, a1.y)), h2u(__floats2half2_rn(a1.z, a1.w)) };
    uint4 u1 = { h2u(__floats2half2_rn(a2.x, a2.y)), h2u(__floats2half2_rn(a2.z, a2.w)),
                 h2u(__floats2half2_rn(a3.x, a3.y)), h2u(__floats2half2_rn(a3.z, a3.w)) };
    *(uint4*)(out + i) = u0;
    *(uint4*)(out + i + 8) = u1;
}
__device__ __forceinline__ void cv16s(const float* __restrict__ in,
                                      __half* __restrict__ out, int i,
                                      int ncol, int ooff) {
    int row = i / ncol, col = i - row * ncol;  // 16-chunk never crosses a row
    float4 a0 = *(const float4*)(in + i);
    float4 a1 = *(const float4*)(in + i + 4);
    float4 a2 = *(const float4*)(in + i + 8);
    float4 a3 = *(const float4*)(in + i + 12);
    uint4 u0 = { h2u(__floats2half2_rn(a0.x, a0.y)), h2u(__floats2half2_rn(a0.z, a0.w)),
                 h2u(__floats2half2_rn(a1.x, a1.y)), h2u(__floats2half2_rn(a1.z, a1.w)) };
    uint4 u1 = { h2u(__floats2half2_rn(a2.x, a2.y)), h2u(__floats2half2_rn(a2.z, a2.w)),
                 h2u(__floats2half2_rn(a3.x, a3.y)), h2u(__floats2half2_rn(a3.z, a3.w)) };
    __half* op = out + (size_t)row * C4_ + ooff + col;
    *(uint4*)op = u0;
    *(uint4*)(op + 8) = u1;
}
// block ranges (4096 elems/block): [0,1024) x, [1024,2048) e,
// [2048,2816) Wqkv->qkvg, [2816,3072) Wg->qkvg, [3072,3328) Ws, [3328,3584) Wp
__global__ void cvt_all(const float* __restrict__ x, const float* __restrict__ e,
                        const float* __restrict__ wqkv, const float* __restrict__ wg,
                        const float* __restrict__ ws, const float* __restrict__ wp,
                        __half* __restrict__ xh, __half* __restrict__ eh,
                        __half* __restrict__ wqkvgh, __half* __restrict__ wsh,
                        __half* __restrict__ wph)
{
    int blk = blockIdx.x;
    int t16 = threadIdx.x * 16;
    if (blk < 1024)            cv16(x, xh, blk * 4096 + t16);
    else if (blk < 2048)       cv16(e, eh, (blk - 1024) * 4096 + t16);
    else if (blk < 2816)       cv16s(wqkv, wqkvgh, (blk - 2048) * 4096 + t16, 3 * C_, 0);
    else if (blk < 3072)       cv16s(wg, wqkvgh, (blk - 2816) * 4096 + t16, C_, 3 * C_);
    else if (blk < 3328)       cv16(ws, wsh, (blk - 3072) * 4096 + t16);
    else                       cv16(wp, wph, (blk - 3328) * 4096 + t16);
}

// ---------------- fp16 GEMM: 128x128 tile, 64x32 warp tile, 3-stage cp.async
#define AS_STRIDE 40
#define BS_STRIDE 136
#define AS_BUF (128 * AS_STRIDE)
#define BS_BUF (32 * BS_STRIDE)
#define NSTAGE 3

template <int BIAS, int HOUT>
__device__ __forceinline__ void gemm_body(
    const __half* __restrict__ A, const __half* __restrict__ Bw,
    const float* __restrict__ bias, void* __restrict__ Cout,
    int Nn, int K, int m_blk, int n_blk, __half* As, __half* Bs)
{
    const int tid = threadIdx.x;
    const int wid = tid >> 5, lane = tid & 31;
    const int wm = (wid & 1) * 64, wn = (wid >> 1) * 32;

    const int arow = tid >> 2, acol = (tid & 3) * 8;   // A: rows arow, arow+64
    const int brow = tid >> 4, bcol = (tid & 15) * 8;  // B: rows brow, brow+16

    auto issue = [&](int kb, int s) {
#pragma unroll
        for (int p = 0; p < 2; p++)
            cpa16(&As[s * AS_BUF + (p * 64 + arow) * AS_STRIDE + acol],
                  A + (size_t)(m_blk + p * 64 + arow) * K + kb * 32 + acol);
#pragma unroll
        for (int p = 0; p < 2; p++)
            cpa16(&Bs[s * BS_BUF + (p * 16 + brow) * BS_STRIDE + bcol],
                  Bw + (size_t)(kb * 32 + p * 16 + brow) * Nn + n_blk + bcol);
        CP_COMMIT();
    };

    float acc[4][4][4] = {};
    issue(0, 0);
    issue(1, 1);

    const int KB = K / 32;
    int s_use = 0;
    for (int kb = 0; kb < KB; kb++) {
        if (kb + 2 < KB) asm volatile("cp.async.wait_group 1;");
        else             asm volatile("cp.async.wait_group 0;");
        __syncthreads();
        if (kb + 2 < KB) {
            int s2 = s_use + 2; if (s2 >= NSTAGE) s2 -= NSTAGE;
            issue(kb + 2, s2);
        }
        const int cs = s_use;
#pragma unroll
        for (int ks = 0; ks < 2; ks++) {
            unsigned af[4][4], bf[4][2];
#pragma unroll
            for (int mt = 0; mt < 4; mt++)
                ldm_x4(af[mt], &As[cs * AS_BUF + (wm + mt * 16 + (lane & 15)) * AS_STRIDE
                                   + ks * 16 + (lane >> 4) * 8]);
#pragma unroll
            for (int sl = 0; sl < 2; sl++) {
                unsigned tr[4];
                ldm_x4t(tr, &Bs[cs * BS_BUF
                                + (ks * 16 + (lane & 7) + ((lane >> 3) & 1) * 8) * BS_STRIDE
                                + wn + sl * 16 + (lane >> 4) * 8]);
                bf[sl * 2 + 0][0] = tr[0]; bf[sl * 2 + 0][1] = tr[1];
                bf[sl * 2 + 1][0] = tr[2]; bf[sl * 2 + 1][1] = tr[3];
            }
#pragma unroll
            for (int mt = 0; mt < 4; mt++)
#pragma unroll
                for (int nt = 0; nt < 4; nt++)
                    mma_h(acc[mt][nt], af[mt], bf[nt]);
        }
        if (++s_use >= NSTAGE) s_use = 0;
    }

    const int g = lane >> 2, t2 = (lane & 3) * 2;
#pragma unroll
    for (int mt = 0; mt < 4; mt++) {
#pragma unroll
        for (int nt = 0; nt < 4; nt++) {
            int col = n_blk + wn + nt * 8 + t2;
            size_t r0 = (size_t)(m_blk + wm + mt * 16 + g);
            if (HOUT) {
                __half* Ch = (__half*)Cout;
                *(__half2*)(Ch + r0 * Nn + col) = __floats2half2_rn(acc[mt][nt][0], acc[mt][nt][1]);
                *(__half2*)(Ch + (r0 + 8) * Nn + col) = __floats2half2_rn(acc[mt][nt][2], acc[mt][nt][3]);
            } else {
                float* Cf = (float*)Cout;
                float b0 = 0.f, b1 = 0.f;
                if (BIAS) { b0 = bias[col]; b1 = bias[col + 1]; }
                float2 v0 = { acc[mt][nt][0] + b0, acc[mt][nt][1] + b1 };
                float2 v1 = { acc[mt][nt][2] + b0, acc[mt][nt][3] + b1 };
                *(float2*)(Cf + r0 * Nn + col) = v0;
                *(float2*)(Cf + (r0 + 8) * Nn + col) = v1;
            }
        }
    }
}

// fused launch: bx<32 -> qkvg = x@[Wqkv|Wg] (N=4C); bx>=32 -> s = e@Ws (N=C)
__global__ __launch_bounds__(256) void gemm_fused(
    const __half* __restrict__ xh, const __half* __restrict__ wqkvg,
    __half* __restrict__ qkvg,
    const __half* __restrict__ eh, const __half* __restrict__ ws,
    __half* __restrict__ sh)
{
    extern __shared__ __half gsm[];
    __half* As = gsm;
    __half* Bs = gsm + NSTAGE * AS_BUF;
    const int bx = blockIdx.x;
    const int m_blk = blockIdx.y * 128;
    if (bx < 32)
        gemm_body<0, 1>(xh, wqkvg, nullptr, qkvg, C4_, C_, m_blk, bx * 128, As, Bs);
    else
        gemm_body<0, 1>(eh, ws, nullptr, sh, C_, C_, m_blk, (bx - 32) * 128, As, Bs);
}

// proj: out = att @ W_proj + bias (fp32 out)
__global__ __launch_bounds__(256) void gemm_proj(
    const __half* __restrict__ atth, const __half* __restrict__ wp,
    const float* __restrict__ bias, float* __restrict__ out)
{
    extern __shared__ __half gsm[];
    __half* As = gsm;
    __half* Bs = gsm + NSTAGE * AS_BUF;
    gemm_body<1, 0>(atth, wp, bias, out, C_, C_, blockIdx.y * 128, blockIdx.x * 128, As, Bs);
}

// ---------------- fp16 flash attention: P in registers (R10-proven) --------
// grid (N/128, H, B), 256 thr (8 warps). Warp w owns q-rows 16w..16w+15.
// qkvg rows have stride 4C: [q | k | v | gate]. Scale folded into Q load.
__global__ __launch_bounds__(256) void flash_h(
    const __half* __restrict__ qkvg, const __half* __restrict__ sb,
    __half* __restrict__ outp)
{
    extern __shared__ __half smh[];
    __half* Qs = smh;                        // [128][72] (staging only)
    __half* Ks = smh + 128 * 72;             // 2 x [64][72]
    __half* Vs = smh + 128 * 72 + 2 * 64 * 72;

    const int qt = blockIdx.x, h = blockIdx.y, b = blockIdx.z;
    const int tid = threadIdx.x;
    const int wid = tid >> 5, lane = tid & 31;
    const size_t qbase = (size_t)(b * N_ + qt * 128);

    const int lr = tid >> 3, lc = (tid & 7) * 8;

    uint4 rk[2], rs[2], rv[2];
    auto ldkv = [&](int kt) {
        const size_t kvb = (size_t)(b * N_ + kt * 64);
#pragma unroll
        for (int p = 0; p < 2; p++) {
            int r = p * 32 + lr;
            rk[p] = *(const uint4*)(qkvg + (kvb + r) * C4_ + C_ + h * D_ + lc);
            rs[p] = *(const uint4*)(sb + (kvb + r) * C_ + h * D_ + lc);
            rv[p] = *(const uint4*)(qkvg + (kvb + r) * C4_ + 2 * C_ + h * D_ + lc);
        }
    };
    auto stkv = [&](int s) {
#pragma unroll
        for (int p = 0; p < 2; p++) {
            int r = p * 32 + lr;
            uint4 u = { hadd2u(rk[p].x, rs[p].x), hadd2u(rk[p].y, rs[p].y),
                        hadd2u(rk[p].z, rs[p].z), hadd2u(rk[p].w, rs[p].w) };
            *(uint4*)&Ks[s * (64 * 72) + r * 72 + lc] = u;
            *(uint4*)&Vs[s * (64 * 72) + r * 72 + lc] = rv[p];
        }
    };

    // ---- prefetch KV tile 0; Q -> smem with scale folded ----
    ldkv(0);
    const __half2 sc2 = __float2half2_rn(SCALE_);
#pragma unroll
    for (int p = 0; p < 4; p++) {
        int r = p * 32 + lr;
        uint4 q4 = *(const uint4*)(qkvg + (qbase + r) * C4_ + h * D_ + lc);
        q4.x = hmul2u(q4.x, sc2); q4.y = hmul2u(q4.y, sc2);
        q4.z = hmul2u(q4.z, sc2); q4.w = hmul2u(q4.w, sc2);
        *(uint4*)&Qs[r * 72 + lc] = q4;
    }
    __syncthreads();

    unsigned qf[4][4];
#pragma unroll
    for (int kd = 0; kd < 4; kd++)
        ldm_x4(qf[kd], &Qs[(wid * 16 + (lane & 15)) * 72 + kd * 16 + (lane >> 4) * 8]);
    stkv(0);
    __syncthreads();

    float o[8][4] = {};
    float m0v = -1e30f, m1v = -1e30f, l0v = 0.f, l1v = 0.f;

    for (int kt = 0; kt < N_ / 64; kt++) {
        const int cs = kt & 1;
        const __half* Kc = Ks + cs * (64 * 72);
        const __half* Vc = Vs + cs * (64 * 72);

        // ---- S = Q (K+s)^T : 16 x 64 per warp (scale pre-folded) ----
        float sc[8][4] = {};
#pragma unroll
        for (int kd = 0; kd < 4; kd++) {
            unsigned bf[8][2];
#pragma unroll
            for (int sp = 0; sp < 4; sp++) {
                unsigned tr[4];
                ldm_x4(tr, &Kc[(sp * 16 + (lane & 7) + (lane >> 4) * 8) * 72
                               + kd * 16 + ((lane >> 3) & 1) * 8]);
                bf[sp * 2 + 0][0] = tr[0]; bf[sp * 2 + 0][1] = tr[1];
                bf[sp * 2 + 1][0] = tr[2]; bf[sp * 2 + 1][1] = tr[3];
            }
#pragma unroll
            for (int nt = 0; nt < 8; nt++)
                mma_h(sc[nt], qf[kd], bf[nt]);
        }

        // ---- online softmax; P built directly as mma A-fragments ----
        float rmax0 = -1e30f, rmax1 = -1e30f;
#pragma unroll
        for (int nt = 0; nt < 8; nt++) {
            rmax0 = fmaxf(rmax0, fmaxf(sc[nt][0], sc[nt][1]));
            rmax1 = fmaxf(rmax1, fmaxf(sc[nt][2], sc[nt][3]));
        }
#pragma unroll
        for (int off = 1; off <= 2; off <<= 1) {
            rmax0 = fmaxf(rmax0, __shfl_xor_sync(~0u, rmax0, off));
            rmax1 = fmaxf(rmax1, __shfl_xor_sync(~0u, rmax1, off));
        }
        float mn0 = fmaxf(m0v, rmax0), mn1 = fmaxf(m1v, rmax1);
        float cf0 = __expf(m0v - mn0), cf1 = __expf(m1v - mn1);
        m0v = mn0; m1v = mn1;
        float rs0 = 0.f, rs1 = 0.f;
        unsigned pf[4][4];
#pragma unroll
        for (int nt = 0; nt < 8; nt++) {
            float p0 = __expf(sc[nt][0] - mn0);
            float p1 = __expf(sc[nt][1] - mn0);
            float p2 = __expf(sc[nt][2] - mn1);
            float p3 = __expf(sc[nt][3] - mn1);
            rs0 += p0 + p1; rs1 += p2 + p3;
            const int kk = nt >> 1, hi = (nt & 1) * 2;
            pf[kk][hi + 0] = h2u(__floats2half2_rn(p0, p1));  // row g
            pf[kk][hi + 1] = h2u(__floats2half2_rn(p2, p3));  // row g+8
        }
#pragma unroll
        for (int off = 1; off <= 2; off <<= 1) {
            rs0 += __shfl_xor_sync(~0u, rs0, off);
            rs1 += __shfl_xor_sync(~0u, rs1, off);
        }
        l0v = l0v * cf0 + rs0;
        l1v = l1v * cf1 + rs1;
#pragma unroll
        for (int nt = 0; nt < 8; nt++) {
            o[nt][0] *= cf0; o[nt][1] *= cf0;
            o[nt][2] *= cf1; o[nt][3] *= cf1;
        }

        // ---- prefetch next KV (sc regs dead; hidden under PV mma) ----
        if (kt + 1 < N_ / 64) ldkv(kt + 1);

        // ---- O += P V  (A fragments straight from registers) ----
#pragma unroll
        for (int kk = 0; kk < 4; kk++) {
            unsigned bf[8][2];
#pragma unroll
            for (int ds = 0; ds < 4; ds++) {
                unsigned tr[4];
                ldm_x4t(tr, &Vc[(kk * 16 + (lane & 7) + ((lane >> 3) & 1) * 8) * 72
                                + ds * 16 + (lane >> 4) * 8]);
                bf[ds * 2 + 0][0] = tr[0]; bf[ds * 2 + 0][1] = tr[1];
                bf[ds * 2 + 1][0] = tr[2]; bf[ds * 2 + 1][1] = tr[3];
            }
#pragma unroll
            for (int nt = 0; nt < 8; nt++)
                mma_h(o[nt], pf[kk], bf[nt]);
        }

        if (kt + 1 < N_ / 64) stkv((kt + 1) & 1);
        __syncthreads();
    }

    // ---- epilogue: normalize, gate (qkvg col 3C), write fp16 att ----
    const int g = lane >> 2, t = lane & 3;
    float inv0 = 1.f / l0v, inv1 = 1.f / l1v;
    size_t r0 = qbase + wid * 16 + g;
#pragma unroll
    for (int nt = 0; nt < 8; nt++) {
        int col = h * D_ + nt * 8 + 2 * t;
        float2 g0 = __half22float2(*(const __half2*)(qkvg + r0 * C4_ + 3 * C_ + col));
        float2 g1 = __half22float2(*(const __half2*)(qkvg + (r0 + 8) * C4_ + 3 * C_ + col));
        *(__half2*)(outp + r0 * C_ + col) =
            __floats2half2_rn(o[nt][0] * inv0 * g0.x, o[nt][1] * inv0 * g0.y);
        *(__half2*)(outp + (r0 + 8) * C_ + col) =
            __floats2half2_rn(o[nt][2] * inv1 * g1.x, o[nt][3] * inv1 * g1.y);
    }
}

// ---------------- launch ------------------------------------------------
extern "C" void kernel_launch(void* const* d_in, const int* in_sizes, int n_in,
                              void* d_out, int out_size)
{
    (void)in_sizes; (void)n_in; (void)out_size;
    const float* x    = (const float*)d_in[0];
    const float* e    = (const float*)d_in[1];
    const float* Wqkv = (const float*)d_in[2];
    const float* Ws   = (const float*)d_in[3];
    const float* Wg   = (const float*)d_in[4];
    const float* Wp   = (const float*)d_in[5];
    const float* bp   = (const float*)d_in[6];
    float* out = (float*)d_out;

    __half *xh, *eh, *wqkvgh, *wsh, *wph, *qkvgh, *sh, *atth;
    cudaGetSymbolAddress((void**)&xh,     g_x_h);
    cudaGetSymbolAddress((void**)&eh,     g_e_h);
    cudaGetSymbolAddress((void**)&wqkvgh, g_wqkvg_h);
    cudaGetSymbolAddress((void**)&wsh,    g_ws_h);
    cudaGetSymbolAddress((void**)&wph,    g_wp_h);
    cudaGetSymbolAddress((void**)&qkvgh,  g_qkvg_h);
    cudaGetSymbolAddress((void**)&sh,     g_s_h);
    cudaGetSymbolAddress((void**)&atth,   g_att_h);

    const int flash_smem = (128 + 2 * 64 + 2 * 64) * 72 * 2;
    const int gemm_smem  = NSTAGE * (AS_BUF + BS_BUF) * 2;
    static int smem_set = 0;
    if (!smem_set) {
        cudaFuncSetAttribute(flash_h, cudaFuncAttributeMaxDynamicSharedMemorySize, flash_smem);
        cudaFuncSetAttribute(gemm_fused, cudaFuncAttributeMaxDynamicSharedMemorySize, gemm_smem);
        cudaFuncSetAttribute(gemm_proj, cudaFuncAttributeMaxDynamicSharedMemorySize, gemm_smem);
        smem_set = 1;
    }

    // 1) all fp32->fp16 conversions in one launch
    cvt_all<<<3584, 256>>>(x, e, Wqkv, Wg, Ws, Wp, xh, eh, wqkvgh, wsh, wph);

    // 2) qkvg = x @ [Wqkv|Wgate]  AND  s = e @ W_s  in one launch
    gemm_fused<<<dim3(40, M_TOT / 128), 256, gemm_smem>>>(xh, wqkvgh, qkvgh, eh, wsh, sh);

    // 3) fused flash attention (k+s fold, scale fold, gate fold, P in regs)
    flash_h<<<dim3(N_ / 128, H_, B_), 256, flash_smem>>>(qkvgh, sh, atth);

    // 4) out = att @ W_proj + b_proj
    gemm_proj<<<dim3(C_ / 128, M_TOT / 128), 256, gemm_smem>>>(atth, wph, bp, out);
}

// round 15
// speedup vs baseline: 1.4708x; 1.0105x over previous
#include <cuda_runtime.h>
#include <cuda_fp16.h>

#define B_ 2
#define N_ 2048
#define C_ 1024
#define H_ 16
#define D_ 64
#define SCALE_ 0.125f
#define M_TOT (B_ * N_)
#define C4_ (4 * C_)

// ---------------- scratch (device globals; no allocation) ----------------
__device__ __half g_x_h[(size_t)M_TOT * C_];
__device__ __half g_e_h[(size_t)M_TOT * C_];
__device__ __half g_wqkvg_h[(size_t)C_ * C4_];     // [K][4C] = [Wqkv | Wgate]
__device__ __half g_ws_h[(size_t)C_ * C_];
__device__ __half g_wp_h[(size_t)C_ * C_];
__device__ __half g_qkvg_h[(size_t)M_TOT * C4_];   // [M][4C] = q|k|v|gate
__device__ __half g_s_h[(size_t)M_TOT * C_];
__device__ __half g_att_h[(size_t)M_TOT * C_];

// ---------------- helpers -------------------------------------------------
__device__ __forceinline__ void ldm_x4(unsigned r[4], const void* p) {
    unsigned a = (unsigned)__cvta_generic_to_shared(p);
    asm volatile("ldmatrix.sync.aligned.m8n8.x4.shared.b16 {%0,%1,%2,%3}, [%4];"
                 : "=r"(r[0]), "=r"(r[1]), "=r"(r[2]), "=r"(r[3]) : "r"(a));
}
__device__ __forceinline__ void ldm_x4t(unsigned r[4], const void* p) {
    unsigned a = (unsigned)__cvta_generic_to_shared(p);
    asm volatile("ldmatrix.sync.aligned.m8n8.x4.trans.shared.b16 {%0,%1,%2,%3}, [%4];"
                 : "=r"(r[0]), "=r"(r[1]), "=r"(r[2]), "=r"(r[3]) : "r"(a));
}
__device__ __forceinline__ void mma_h(float c[4], const unsigned a[4], const unsigned b[2]) {
    asm volatile("mma.sync.aligned.m16n8k16.row.col.f32.f16.f16.f32 "
                 "{%0,%1,%2,%3}, {%4,%5,%6,%7}, {%8,%9}, {%0,%1,%2,%3};"
                 : "+f"(c[0]), "+f"(c[1]), "+f"(c[2]), "+f"(c[3])
                 : "r"(a[0]), "r"(a[1]), "r"(a[2]), "r"(a[3]), "r"(b[0]), "r"(b[1]));
}
__device__ __forceinline__ unsigned h2u(__half2 h) { return *reinterpret_cast<unsigned*>(&h); }
__device__ __forceinline__ unsigned hadd2u(unsigned a, unsigned b) {
    __half2 r = __hadd2(*reinterpret_cast<__half2*>(&a), *reinterpret_cast<__half2*>(&b));
    return h2u(r);
}
__device__ __forceinline__ unsigned hmul2u(unsigned a, __half2 s) {
    __half2 r = __hmul2(*reinterpret_cast<__half2*>(&a), s);
    return h2u(r);
}
__device__ __forceinline__ void cpa16(__half* dst, const __half* src) {
    unsigned d = (unsigned)__cvta_generic_to_shared(dst);
    asm volatile("cp.async.cg.shared.global [%0], [%1], 16;" :: "r"(d), "l"(src));
}
#define CP_COMMIT() asm volatile("cp.async.commit_group;")

// ---------------- fused fp32 -> fp16 convert (16 elems/thread, MLP=4) ------
__device__ __forceinline__ void cv16(const float* __restrict__ in,
                                     __half* __restrict__ out, int i) {
    float4 a0 = *(const float4*)(in + i);
    float4 a1 = *(const float4*)(in + i + 4);
    float4 a2 = *(const float4*)(in + i + 8);
    float4 a3 = *(const float4*)(in + i + 12);
    uint4 u0 = { h2u(__floats2half2_rn(a0.x, a0.y)), h2u(__floats2half2_rn(a0.z, a0.w)),
                 h2u(__floats2half2_rn(a1.x, a1.y)), h2u(__floats2half2_rn(a1.z, a1.w)) };
    uint4 u1 = { h2u(__floats2half2_rn(a2.x, a2.y)), h2u(__floats2half2_rn(a2.z, a2.w)),
                 h2u(__floats2half2_rn(a3.x, a3.y)), h2u(__floats2half2_rn(a3.z, a3.w)) };
    *(uint4*)(out + i) = u0;
    *(uint4*)(out + i + 8) = u1;
}
__device__ __forceinline__ void cv16s(const float* __restrict__ in,
                                      __half* __restrict__ out, int i,
                                      int ncol, int ooff) {
    int row = i / ncol, col = i - row * ncol;  // 16-chunk never crosses a row
    float4 a0 = *(const float4*)(in + i);
    float4 a1 = *(const float4*)(in + i + 4);
    float4 a2 = *(const float4*)(in + i + 8);
    float4 a3 = *(const float4*)(in + i + 12);
    uint4 u0 = { h2u(__floats2half2_rn(a0.x, a0.y)), h2u(__floats2half2_rn(a0.z, a0.w)),
                 h2u(__floats2half2_rn(a1.x, a1.y)), h2u(__floats2half2_rn(a1.z, a1.w)) };
    uint4 u1 = { h2u(__floats2half2_rn(a2.x, a2.y)), h2u(__floats2half2_rn(a2.z, a2.w)),
                 h2u(__floats2half2_rn(a3.x, a3.y)), h2u(__floats2half2_rn(a3.z, a3.w)) };
    __half* op = out + (size_t)row * C4_ + ooff + col;
    *(uint4*)op = u0;
    *(uint4*)(op + 8) = u1;
}
// block ranges (4096 elems/block): [0,1024) x, [1024,2048) e,
// [2048,2816) Wqkv->qkvg, [2816,3072) Wg->qkvg, [3072,3328) Ws, [3328,3584) Wp
__global__ void cvt_all(const float* __restrict__ x, const float* __restrict__ e,
                        const float* __restrict__ wqkv, const float* __restrict__ wg,
                        const float* __restrict__ ws, const float* __restrict__ wp,
                        __half* __restrict__ xh, __half* __restrict__ eh,
                        __half* __restrict__ wqkvgh, __half* __restrict__ wsh,
                        __half* __restrict__ wph)
{
    int blk = blockIdx.x;
    int t16 = threadIdx.x * 16;
    if (blk < 1024)            cv16(x, xh, blk * 4096 + t16);
    else if (blk < 2048)       cv16(e, eh, (blk - 1024) * 4096 + t16);
    else if (blk < 2816)       cv16s(wqkv, wqkvgh, (blk - 2048) * 4096 + t16, 3 * C_, 0);
    else if (blk < 3072)       cv16s(wg, wqkvgh, (blk - 2816) * 4096 + t16, C_, 3 * C_);
    else if (blk < 3328)       cv16(ws, wsh, (blk - 3072) * 4096 + t16);
    else                       cv16(wp, wph, (blk - 3328) * 4096 + t16);
}

// ---------------- fp16 GEMM: 64x128 tile, 32x32 warp tile, 3-stage cp.async
// 256 thr (8 warps, 2x4), 3 blocks/SM (24 warps) for latency hiding.
#define AS_STRIDE 40
#define BS_STRIDE 136
#define AS_BUF (64 * AS_STRIDE)
#define BS_BUF (32 * BS_STRIDE)
#define NSTAGE 3

template <int BIAS, int HOUT>
__device__ __forceinline__ void gemm_body(
    const __half* __restrict__ A, const __half* __restrict__ Bw,
    const float* __restrict__ bias, void* __restrict__ Cout,
    int Nn, int K, int m_blk, int n_blk, __half* As, __half* Bs)
{
    const int tid = threadIdx.x;
    const int wid = tid >> 5, lane = tid & 31;
    const int wm = (wid & 1) * 32, wn = (wid >> 1) * 32;

    const int arow = tid >> 2, acol = (tid & 3) * 8;   // A: 64 rows, 1 chunk/thread
    const int brow = tid >> 4, bcol = (tid & 15) * 8;  // B: rows brow, brow+16

    auto issue = [&](int kb, int s) {
        cpa16(&As[s * AS_BUF + arow * AS_STRIDE + acol],
              A + (size_t)(m_blk + arow) * K + kb * 32 + acol);
#pragma unroll
        for (int p = 0; p < 2; p++)
            cpa16(&Bs[s * BS_BUF + (p * 16 + brow) * BS_STRIDE + bcol],
                  Bw + (size_t)(kb * 32 + p * 16 + brow) * Nn + n_blk + bcol);
        CP_COMMIT();
    };

    float acc[2][4][4] = {};
    issue(0, 0);
    issue(1, 1);

    const int KB = K / 32;
    int s_use = 0;
    for (int kb = 0; kb < KB; kb++) {
        if (kb + 2 < KB) asm volatile("cp.async.wait_group 1;");
        else             asm volatile("cp.async.wait_group 0;");
        __syncthreads();
        if (kb + 2 < KB) {
            int s2 = s_use + 2; if (s2 >= NSTAGE) s2 -= NSTAGE;
            issue(kb + 2, s2);
        }
        const int cs = s_use;
#pragma unroll
        for (int ks = 0; ks < 2; ks++) {
            unsigned af[2][4], bf[4][2];
#pragma unroll
            for (int mt = 0; mt < 2; mt++)
                ldm_x4(af[mt], &As[cs * AS_BUF + (wm + mt * 16 + (lane & 15)) * AS_STRIDE
                                   + ks * 16 + (lane >> 4) * 8]);
#pragma unroll
            for (int sl = 0; sl < 2; sl++) {
                unsigned tr[4];
                ldm_x4t(tr, &Bs[cs * BS_BUF
                                + (ks * 16 + (lane & 7) + ((lane >> 3) & 1) * 8) * BS_STRIDE
                                + wn + sl * 16 + (lane >> 4) * 8]);
                bf[sl * 2 + 0][0] = tr[0]; bf[sl * 2 + 0][1] = tr[1];
                bf[sl * 2 + 1][0] = tr[2]; bf[sl * 2 + 1][1] = tr[3];
            }
#pragma unroll
            for (int mt = 0; mt < 2; mt++)
#pragma unroll
                for (int nt = 0; nt < 4; nt++)
                    mma_h(acc[mt][nt], af[mt], bf[nt]);
        }
        if (++s_use >= NSTAGE) s_use = 0;
    }

    const int g = lane >> 2, t2 = (lane & 3) * 2;
#pragma unroll
    for (int mt = 0; mt < 2; mt++) {
#pragma unroll
        for (int nt = 0; nt < 4; nt++) {
            int col = n_blk + wn + nt * 8 + t2;
            size_t r0 = (size_t)(m_blk + wm + mt * 16 + g);
            if (HOUT) {
                __half* Ch = (__half*)Cout;
                *(__half2*)(Ch + r0 * Nn + col) = __floats2half2_rn(acc[mt][nt][0], acc[mt][nt][1]);
                *(__half2*)(Ch + (r0 + 8) * Nn + col) = __floats2half2_rn(acc[mt][nt][2], acc[mt][nt][3]);
            } else {
                float* Cf = (float*)Cout;
                float b0 = 0.f, b1 = 0.f;
                if (BIAS) { b0 = bias[col]; b1 = bias[col + 1]; }
                float2 v0 = { acc[mt][nt][0] + b0, acc[mt][nt][1] + b1 };
                float2 v1 = { acc[mt][nt][2] + b0, acc[mt][nt][3] + b1 };
                *(float2*)(Cf + r0 * Nn + col) = v0;
                *(float2*)(Cf + (r0 + 8) * Nn + col) = v1;
            }
        }
    }
}

// fused launch: bx<32 -> qkvg = x@[Wqkv|Wg] (N=4C); bx>=32 -> s = e@Ws (N=C)
__global__ __launch_bounds__(256, 3) void gemm_fused(
    const __half* __restrict__ xh, const __half* __restrict__ wqkvg,
    __half* __restrict__ qkvg,
    const __half* __restrict__ eh, const __half* __restrict__ ws,
    __half* __restrict__ sh)
{
    extern __shared__ __half gsm[];
    __half* As = gsm;
    __half* Bs = gsm + NSTAGE * AS_BUF;
    const int bx = blockIdx.x;
    const int m_blk = blockIdx.y * 64;
    if (bx < 32)
        gemm_body<0, 1>(xh, wqkvg, nullptr, qkvg, C4_, C_, m_blk, bx * 128, As, Bs);
    else
        gemm_body<0, 1>(eh, ws, nullptr, sh, C_, C_, m_blk, (bx - 32) * 128, As, Bs);
}

// proj: out = att @ W_proj + bias (fp32 out)
__global__ __launch_bounds__(256, 3) void gemm_proj(
    const __half* __restrict__ atth, const __half* __restrict__ wp,
    const float* __restrict__ bias, float* __restrict__ out)
{
    extern __shared__ __half gsm[];
    __half* As = gsm;
    __half* Bs = gsm + NSTAGE * AS_BUF;
    gemm_body<1, 0>(atth, wp, bias, out, C_, C_, blockIdx.y * 64, blockIdx.x * 128, As, Bs);
}

// ---------------- fp16 flash attention: P in registers (R10-proven) --------
// grid (N/128, H, B), 256 thr (8 warps). Warp w owns q-rows 16w..16w+15.
// qkvg rows have stride 4C: [q | k | v | gate]. Scale folded into Q load.
__global__ __launch_bounds__(256) void flash_h(
    const __half* __restrict__ qkvg, const __half* __restrict__ sb,
    __half* __restrict__ outp)
{
    extern __shared__ __half smh[];
    __half* Qs = smh;                        // [128][72] (staging only)
    __half* Ks = smh + 128 * 72;             // 2 x [64][72]
    __half* Vs = smh + 128 * 72 + 2 * 64 * 72;

    const int qt = blockIdx.x, h = blockIdx.y, b = blockIdx.z;
    const int tid = threadIdx.x;
    const int wid = tid >> 5, lane = tid & 31;
    const size_t qbase = (size_t)(b * N_ + qt * 128);

    const int lr = tid >> 3, lc = (tid & 7) * 8;

    uint4 rk[2], rs[2], rv[2];
    auto ldkv = [&](int kt) {
        const size_t kvb = (size_t)(b * N_ + kt * 64);
#pragma unroll
        for (int p = 0; p < 2; p++) {
            int r = p * 32 + lr;
            rk[p] = *(const uint4*)(qkvg + (kvb + r) * C4_ + C_ + h * D_ + lc);
            rs[p] = *(const uint4*)(sb + (kvb + r) * C_ + h * D_ + lc);
            rv[p] = *(const uint4*)(qkvg + (kvb + r) * C4_ + 2 * C_ + h * D_ + lc);
        }
    };
    auto stkv = [&](int s) {
#pragma unroll
        for (int p = 0; p < 2; p++) {
            int r = p * 32 + lr;
            uint4 u = { hadd2u(rk[p].x, rs[p].x), hadd2u(rk[p].y, rs[p].y),
                        hadd2u(rk[p].z, rs[p].z), hadd2u(rk[p].w, rs[p].w) };
            *(uint4*)&Ks[s * (64 * 72) + r * 72 + lc] = u;
            *(uint4*)&Vs[s * (64 * 72) + r * 72 + lc] = rv[p];
        }
    };

    // ---- prefetch KV tile 0; Q -> smem with scale folded ----
    ldkv(0);
    const __half2 sc2 = __float2half2_rn(SCALE_);
#pragma unroll
    for (int p = 0; p < 4; p++) {
        int r = p * 32 + lr;
        uint4 q4 = *(const uint4*)(qkvg + (qbase + r) * C4_ + h * D_ + lc);
        q4.x = hmul2u(q4.x, sc2); q4.y = hmul2u(q4.y, sc2);
        q4.z = hmul2u(q4.z, sc2); q4.w = hmul2u(q4.w, sc2);
        *(uint4*)&Qs[r * 72 + lc] = q4;
    }
    __syncthreads();

    unsigned qf[4][4];
#pragma unroll
    for (int kd = 0; kd < 4; kd++)
        ldm_x4(qf[kd], &Qs[(wid * 16 + (lane & 15)) * 72 + kd * 16 + (lane >> 4) * 8]);
    stkv(0);
    __syncthreads();

    float o[8][4] = {};
    float m0v = -1e30f, m1v = -1e30f, l0v = 0.f, l1v = 0.f;

    for (int kt = 0; kt < N_ / 64; kt++) {
        const int cs = kt & 1;
        const __half* Kc = Ks + cs * (64 * 72);
        const __half* Vc = Vs + cs * (64 * 72);

        // ---- S = Q (K+s)^T : 16 x 64 per warp (scale pre-folded) ----
        float sc[8][4] = {};
#pragma unroll
        for (int kd = 0; kd < 4; kd++) {
            unsigned bf[8][2];
#pragma unroll
            for (int sp = 0; sp < 4; sp++) {
                unsigned tr[4];
                ldm_x4(tr, &Kc[(sp * 16 + (lane & 7) + (lane >> 4) * 8) * 72
                               + kd * 16 + ((lane >> 3) & 1) * 8]);
                bf[sp * 2 + 0][0] = tr[0]; bf[sp * 2 + 0][1] = tr[1];
                bf[sp * 2 + 1][0] = tr[2]; bf[sp * 2 + 1][1] = tr[3];
            }
#pragma unroll
            for (int nt = 0; nt < 8; nt++)
                mma_h(sc[nt], qf[kd], bf[nt]);
        }

        // ---- online softmax; P built directly as mma A-fragments ----
        float rmax0 = -1e30f, rmax1 = -1e30f;
#pragma unroll
        for (int nt = 0; nt < 8; nt++) {
            rmax0 = fmaxf(rmax0, fmaxf(sc[nt][0], sc[nt][1]));
            rmax1 = fmaxf(rmax1, fmaxf(sc[nt][2], sc[nt][3]));
        }
#pragma unroll
        for (int off = 1; off <= 2; off <<= 1) {
            rmax0 = fmaxf(rmax0, __shfl_xor_sync(~0u, rmax0, off));
            rmax1 = fmaxf(rmax1, __shfl_xor_sync(~0u, rmax1, off));
        }
        float mn0 = fmaxf(m0v, rmax0), mn1 = fmaxf(m1v, rmax1);
        float cf0 = __expf(m0v - mn0), cf1 = __expf(m1v - mn1);
        m0v = mn0; m1v = mn1;
        float rs0 = 0.f, rs1 = 0.f;
        unsigned pf[4][4];
#pragma unroll
        for (int nt = 0; nt < 8; nt++) {
            float p0 = __expf(sc[nt][0] - mn0);
            float p1 = __expf(sc[nt][1] - mn0);
            float p2 = __expf(sc[nt][2] - mn1);
            float p3 = __expf(sc[nt][3] - mn1);
            rs0 += p0 + p1; rs1 += p2 + p3;
            const int kk = nt >> 1, hi = (nt & 1) * 2;
            pf[kk][hi + 0] = h2u(__floats2half2_rn(p0, p1));  // row g
            pf[kk][hi + 1] = h2u(__floats2half2_rn(p2, p3));  // row g+8
        }
#pragma unroll
        for (int off = 1; off <= 2; off <<= 1) {
            rs0 += __shfl_xor_sync(~0u, rs0, off);
            rs1 += __shfl_xor_sync(~0u, rs1, off);
        }
        l0v = l0v * cf0 + rs0;
        l1v = l1v * cf1 + rs1;
#pragma unroll
        for (int nt = 0; nt < 8; nt++) {
            o[nt][0] *= cf0; o[nt][1] *= cf0;
            o[nt][2] *= cf1; o[nt][3] *= cf1;
        }

        // ---- prefetch next KV (sc regs dead; hidden under PV mma) ----
        if (kt + 1 < N_ / 64) ldkv(kt + 1);

        // ---- O += P V  (A fragments straight from registers) ----
#pragma unroll
        for (int kk = 0; kk < 4; kk++) {
            unsigned bf[8][2];
#pragma unroll
            for (int ds = 0; ds < 4; ds++) {
                unsigned tr[4];
                ldm_x4t(tr, &Vc[(kk * 16 + (lane & 7) + ((lane >> 3) & 1) * 8) * 72
                                + ds * 16 + (lane >> 4) * 8]);
                bf[ds * 2 + 0][0] = tr[0]; bf[ds * 2 + 0][1] = tr[1];
                bf[ds * 2 + 1][0] = tr[2]; bf[ds * 2 + 1][1] = tr[3];
            }
#pragma unroll
            for (int nt = 0; nt < 8; nt++)
                mma_h(o[nt], pf[kk], bf[nt]);
        }

        if (kt + 1 < N_ / 64) stkv((kt + 1) & 1);
        __syncthreads();
    }

    // ---- epilogue: normalize, gate (qkvg col 3C), write fp16 att ----
    const int g = lane >> 2, t = lane & 3;
    float inv0 = 1.f / l0v, inv1 = 1.f / l1v;
    size_t r0 = qbase + wid * 16 + g;
#pragma unroll
    for (int nt = 0; nt < 8; nt++) {
        int col = h * D_ + nt * 8 + 2 * t;
        float2 g0 = __half22float2(*(const __half2*)(qkvg + r0 * C4_ + 3 * C_ + col));
        float2 g1 = __half22float2(*(const __half2*)(qkvg + (r0 + 8) * C4_ + 3 * C_ + col));
        *(__half2*)(outp + r0 * C_ + col) =
            __floats2half2_rn(o[nt][0] * inv0 * g0.x, o[nt][1] * inv0 * g0.y);
        *(__half2*)(outp + (r0 + 8) * C_ + col) =
            __floats2half2_rn(o[nt][2] * inv1 * g1.x, o[nt][3] * inv1 * g1.y);
    }
}

// ---------------- launch ------------------------------------------------
extern "C" void kernel_launch(void* const* d_in, const int* in_sizes, int n_in,
                              void* d_out, int out_size)
{
    (void)in_sizes; (void)n_in; (void)out_size;
    const float* x    = (const float*)d_in[0];
    const float* e    = (const float*)d_in[1];
    const float* Wqkv = (const float*)d_in[2];
    const float* Ws   = (const float*)d_in[3];
    const float* Wg   = (const float*)d_in[4];
    const float* Wp   = (const float*)d_in[5];
    const float* bp   = (const float*)d_in[6];
    float* out = (float*)d_out;

    __half *xh, *eh, *wqkvgh, *wsh, *wph, *qkvgh, *sh, *atth;
    cudaGetSymbolAddress((void**)&xh,     g_x_h);
    cudaGetSymbolAddress((void**)&eh,     g_e_h);
    cudaGetSymbolAddress((void**)&wqkvgh, g_wqkvg_h);
    cudaGetSymbolAddress((void**)&wsh,    g_ws_h);
    cudaGetSymbolAddress((void**)&wph,    g_wp_h);
    cudaGetSymbolAddress((void**)&qkvgh,  g_qkvg_h);
    cudaGetSymbolAddress((void**)&sh,     g_s_h);
    cudaGetSymbolAddress((void**)&atth,   g_att_h);

    const int flash_smem = (128 + 2 * 64 + 2 * 64) * 72 * 2;
    const int gemm_smem  = NSTAGE * (AS_BUF + BS_BUF) * 2;
    static int smem_set = 0;
    if (!smem_set) {
        cudaFuncSetAttribute(flash_h, cudaFuncAttributeMaxDynamicSharedMemorySize, flash_smem);
        cudaFuncSetAttribute(gemm_fused, cudaFuncAttributeMaxDynamicSharedMemorySize, gemm_smem);
        cudaFuncSetAttribute(gemm_proj, cudaFuncAttributeMaxDynamicSharedMemorySize, gemm_smem);
        smem_set = 1;
    }

    // 1) all fp32->fp16 conversions in one launch
    cvt_all<<<3584, 256>>>(x, e, Wqkv, Wg, Ws, Wp, xh, eh, wqkvgh, wsh, wph);

    // 2) qkvg = x @ [Wqkv|Wgate]  AND  s = e @ W_s  in one launch (64-row tiles)
    gemm_fused<<<dim3(40, M_TOT / 64), 256, gemm_smem>>>(xh, wqkvgh, qkvgh, eh, wsh, sh);

    // 3) fused flash attention (k+s fold, scale fold, gate fold, P in regs)
    flash_h<<<dim3(N_ / 128, H_, B_), 256, flash_smem>>>(qkvgh, sh, atth);

    // 4) out = att @ W_proj + b_proj
    gemm_proj<<<dim3(C_ / 128, M_TOT / 64), 256, gemm_smem>>>(atth, wph, bp, out);
}